// round 13
// baseline (speedup 1.0000x reference)
#include <cuda_runtime.h>
#include <mma.h>
#include <cstdint>

using namespace nvcuda;

// ---------------------------------------------------------------------------
// CausalSelfAttention  B=4, T=2048, C=1024, H=16, Dh=64
// R13: GEMMs unchanged (R3/R12 proven). Attention rebuilt with Br=128 Q-tiles,
//      512 threads / 16 warps: halves iteration count (528->272 per bh),
//      4 barriers/iter, warp-local PV staging through disjoint Ss regions.
// ---------------------------------------------------------------------------

#define D_MODEL 1024
#define N_HEADS 16
#define HEAD_DIM 64
#define BATCH 4
#define SEQ 2048
#define MTOT (BATCH * SEQ)   // 8192
#define C3 (3 * D_MODEL)     // 3072

__device__ float g_qkv[(size_t)MTOT * C3];      // 96 MB
__device__ float g_y[(size_t)MTOT * D_MODEL];   // 32 MB

// ---------------------------------------------------------------------------
// TF32 GEMM (R3/R12, proven): C[M,N] = A[M,K] @ B[K,N] + bias[N]
// ---------------------------------------------------------------------------
#define AS_LD 40
#define BS_LD 136
#define EB_LD 24

__device__ __forceinline__ void tf32_gemm_body(const float* __restrict__ A,
                                               const float* __restrict__ B,
                                               const float* __restrict__ bias,
                                               float* __restrict__ C,
                                               int N, int K)
{
    __shared__ float As[128 * AS_LD];
    __shared__ float Bs[32 * BS_LD];

    const int tid  = threadIdx.x;
    const int lane = tid & 31;
    const int warp = tid >> 5;
    const int wm = warp >> 2;
    const int wn = warp & 3;

    const int bm = blockIdx.y * 128;
    const int bn = blockIdx.x * 128;

    const int aRow = tid >> 1;
    const int aCol = (tid & 1) * 16;
    const int bRow = tid >> 3;
    const int bCol = (tid & 7) * 16;

    const float* Ap = A + (size_t)(bm + aRow) * K + aCol;
    const float* Bp = B + (size_t)bRow * N + bn + bCol;

    wmma::fragment<wmma::accumulator, 16, 16, 8, float> acc[4][2];
#pragma unroll
    for (int i = 0; i < 4; i++)
#pragma unroll
        for (int j = 0; j < 2; j++) wmma::fill_fragment(acc[i][j], 0.0f);

    for (int k0 = 0; k0 < K; k0 += 32) {
#pragma unroll
        for (int v = 0; v < 4; v++) {
            float4 a4 = *(const float4*)(Ap + k0 + v * 4);
            float* d = &As[aRow * AS_LD + aCol + v * 4];
            d[0] = wmma::__float_to_tf32(a4.x);
            d[1] = wmma::__float_to_tf32(a4.y);
            d[2] = wmma::__float_to_tf32(a4.z);
            d[3] = wmma::__float_to_tf32(a4.w);
        }
#pragma unroll
        for (int v = 0; v < 4; v++) {
            float4 b4 = *(const float4*)(Bp + (size_t)k0 * N + v * 4);
            float* d = &Bs[bRow * BS_LD + bCol + v * 4];
            d[0] = wmma::__float_to_tf32(b4.x);
            d[1] = wmma::__float_to_tf32(b4.y);
            d[2] = wmma::__float_to_tf32(b4.z);
            d[3] = wmma::__float_to_tf32(b4.w);
        }
        __syncthreads();

#pragma unroll
        for (int kk = 0; kk < 32; kk += 8) {
            wmma::fragment<wmma::matrix_b, 16, 16, 8, wmma::precision::tf32,
                           wmma::row_major> bf[2];
            wmma::load_matrix_sync(bf[0], &Bs[kk * BS_LD + wn * 32 + 0],  BS_LD);
            wmma::load_matrix_sync(bf[1], &Bs[kk * BS_LD + wn * 32 + 16], BS_LD);
#pragma unroll
            for (int i = 0; i < 4; i++) {
                wmma::fragment<wmma::matrix_a, 16, 16, 8, wmma::precision::tf32,
                               wmma::row_major> af;
                wmma::load_matrix_sync(af, &As[(wm * 64 + i * 16) * AS_LD + kk], AS_LD);
                wmma::mma_sync(acc[i][0], af, bf[0], acc[i][0]);
                wmma::mma_sync(acc[i][1], af, bf[1], acc[i][1]);
            }
        }
        __syncthreads();
    }

    float* eb = &As[warp * 16 * EB_LD];
    const int er = lane >> 1;
    const int ec = (lane & 1) * 8;

#pragma unroll
    for (int i = 0; i < 4; i++) {
#pragma unroll
        for (int j = 0; j < 2; j++) {
            wmma::store_matrix_sync(eb, acc[i][j], EB_LD, wmma::mem_row_major);
            __syncwarp();
            const int row = bm + wm * 64 + i * 16 + er;
            const int col = bn + wn * 32 + j * 16 + ec;
            float4 v0 = *(const float4*)&eb[er * EB_LD + ec];
            float4 v1 = *(const float4*)&eb[er * EB_LD + ec + 4];
            float4 b0 = *(const float4*)&bias[col];
            float4 b1 = *(const float4*)&bias[col + 4];
            v0.x += b0.x; v0.y += b0.y; v0.z += b0.z; v0.w += b0.w;
            v1.x += b1.x; v1.y += b1.y; v1.z += b1.z; v1.w += b1.w;
            *(float4*)&C[(size_t)row * N + col]     = v0;
            *(float4*)&C[(size_t)row * N + col + 4] = v1;
            __syncwarp();
        }
    }
}

__global__ __launch_bounds__(256) void qkv_gemm_kernel(const float* __restrict__ x,
                                                       const float* __restrict__ W,
                                                       const float* __restrict__ bias)
{
    tf32_gemm_body(x, W, bias, g_qkv, C3, D_MODEL);
}

__global__ __launch_bounds__(256) void out_gemm_kernel(const float* __restrict__ W,
                                                       const float* __restrict__ bias,
                                                       float* __restrict__ out)
{
    tf32_gemm_body(g_y, W, bias, out, D_MODEL, D_MODEL);
}

// ---------------------------------------------------------------------------
// TF32 wmma flash attention, Br=128 x Bc=64.
// Grid (T/128, B*H). Block 512 thr = 16 warps; warp tile 16 rows x 32 cols.
// Smem rows (stride APAD=72, wmma-proven): Qs[128], Os[128], Ss[128],
// Ks[64], Vs[64]; stats m/l/corr[128]. ~149 KB -> 1 block/SM (16 warps).
// 4 barriers/iter; PV results staged warp-locally through Ss.
// ---------------------------------------------------------------------------
#define APAD 72
#define A_QS 0
#define A_OS (128 * APAD)
#define A_SS (2 * 128 * APAD)
#define A_KS (3 * 128 * APAD)
#define A_VS (3 * 128 * APAD + 64 * APAD)
#define A_STATS (3 * 128 * APAD + 2 * 64 * APAD)
#define ATTN_SMEM_BYTES ((A_STATS + 3 * 128) * (int)sizeof(float))  // 148992

__global__ __launch_bounds__(512) void attn_kernel()
{
    extern __shared__ float sm[];
    float* Qs = sm + A_QS;
    float* Os = sm + A_OS;
    float* Ss = sm + A_SS;
    float* Ks = sm + A_KS;
    float* Vs = sm + A_VS;
    float* m_s    = sm + A_STATS;        // [128]
    float* l_s    = m_s + 128;
    float* corr_s = l_s + 128;

    const int qt2 = blockIdx.x;          // 0..15
    const int b   = blockIdx.y >> 4;
    const int h   = blockIdx.y & 15;
    const int tid  = threadIdx.x;
    const int lane = tid & 31;
    const int warp = tid >> 5;           // 0..15
    const int sr = (warp >> 1) * 16;     // row base (0..112)
    const int sc = (warp & 1) * 32;      // col base (0 or 32)
    const int qbase = qt2 * 128;
    const int nkt = 2 * qt2 + 2;

    const float* qkvb = g_qkv + (size_t)b * SEQ * C3 + h * HEAD_DIM;

    // Load Q tile [128][64] (tf32 cvt) + init O/stats
    for (int idx = tid; idx < 128 * 16; idx += 512) {
        int i = idx >> 4, d4 = (idx & 15) * 4;
        float4 q = *(const float4*)&qkvb[(size_t)(qbase + i) * C3 + d4];
        q.x = wmma::__float_to_tf32(q.x);
        q.y = wmma::__float_to_tf32(q.y);
        q.z = wmma::__float_to_tf32(q.z);
        q.w = wmma::__float_to_tf32(q.w);
        *(float4*)&Qs[i * APAD + d4] = q;
        *(float4*)&Os[i * APAD + d4] = make_float4(0.f, 0.f, 0.f, 0.f);
    }
    if (tid < 128) { m_s[tid] = -1e30f; l_s[tid] = 0.0f; }

    for (int kt = 0; kt < nkt; ++kt) {
        const int kbase = kt * 64;
        const bool maskt = (kt + 2 >= nkt);   // last two tiles touch diagonal

        // ---- stage K/V tile [64][64] (tf32 cvt) ----
        for (int idx = tid; idx < 64 * 16; idx += 512) {
            int j = idx >> 4, d4 = (idx & 15) * 4;
            size_t off = (size_t)(kbase + j) * C3 + d4;
            float4 k = *(const float4*)&qkvb[off + D_MODEL];
            float4 v = *(const float4*)&qkvb[off + 2 * D_MODEL];
            k.x = wmma::__float_to_tf32(k.x);
            k.y = wmma::__float_to_tf32(k.y);
            k.z = wmma::__float_to_tf32(k.z);
            k.w = wmma::__float_to_tf32(k.w);
            v.x = wmma::__float_to_tf32(v.x);
            v.y = wmma::__float_to_tf32(v.y);
            v.z = wmma::__float_to_tf32(v.z);
            v.w = wmma::__float_to_tf32(v.w);
            *(float4*)&Ks[j * APAD + d4] = k;
            *(float4*)&Vs[j * APAD + d4] = v;
        }
        __syncthreads();   // (1) staging done; also fences prev-iter Ss readback

        // ---- S = Q @ K^T : warp computes rows [sr,sr+16) x cols [sc,sc+32) --
        {
            wmma::fragment<wmma::accumulator, 16, 16, 8, float> sacc[2];
            wmma::fill_fragment(sacc[0], 0.0f);
            wmma::fill_fragment(sacc[1], 0.0f);
#pragma unroll
            for (int kk = 0; kk < 64; kk += 8) {
                wmma::fragment<wmma::matrix_a, 16, 16, 8, wmma::precision::tf32,
                               wmma::row_major> af;
                wmma::load_matrix_sync(af, &Qs[sr * APAD + kk], APAD);
                wmma::fragment<wmma::matrix_b, 16, 16, 8, wmma::precision::tf32,
                               wmma::col_major> bf0, bf1;
                wmma::load_matrix_sync(bf0, &Ks[(sc + 0)  * APAD + kk], APAD);
                wmma::load_matrix_sync(bf1, &Ks[(sc + 16) * APAD + kk], APAD);
                wmma::mma_sync(sacc[0], af, bf0, sacc[0]);
                wmma::mma_sync(sacc[1], af, bf1, sacc[1]);
            }
            wmma::store_matrix_sync(&Ss[sr * APAD + sc],      sacc[0], APAD,
                                    wmma::mem_row_major);
            wmma::store_matrix_sync(&Ss[sr * APAD + sc + 16], sacc[1], APAD,
                                    wmma::mem_row_major);
        }
        __syncthreads();   // (2) all of S visible

        // ---- online softmax: 4 threads per row (128 rows), 16 cols each ----
        {
            const int r   = tid >> 2;
            const int c16 = (tid & 3) * 16;
            const float scale = 0.125f;   // 1/sqrt(64)
            float sv[16];
            float tmax = -1e30f;
#pragma unroll
            for (int c = 0; c < 16; c++) {
                float s = Ss[r * APAD + c16 + c] * scale;
                if (maskt && (kbase + c16 + c) > (qbase + r)) s = -1e30f;
                sv[c] = s;
                tmax = fmaxf(tmax, s);
            }
            tmax = fmaxf(tmax, __shfl_xor_sync(0xffffffffu, tmax, 1));
            tmax = fmaxf(tmax, __shfl_xor_sync(0xffffffffu, tmax, 2));
            const float mold = m_s[r];
            const float nm = fmaxf(mold, tmax);
            float rs = 0.0f;
#pragma unroll
            for (int c = 0; c < 16; c++) {
                float p = __expf(sv[c] - nm);
                Ss[r * APAD + c16 + c] = wmma::__float_to_tf32(p);
                rs += p;
            }
            rs += __shfl_xor_sync(0xffffffffu, rs, 1);
            rs += __shfl_xor_sync(0xffffffffu, rs, 2);
            if ((tid & 3) == 0) {
                const float corr = __expf(mold - nm);
                m_s[r] = nm;
                l_s[r] = l_s[r] * corr + rs;
                corr_s[r] = corr;
            }
        }
        __syncthreads();   // (3) P + stats visible

        // ---- PV = P @ V : rows [sr,sr+16) x cols [sc,sc+32) ----
        wmma::fragment<wmma::accumulator, 16, 16, 8, float> oacc[2];
        wmma::fill_fragment(oacc[0], 0.0f);
        wmma::fill_fragment(oacc[1], 0.0f);
#pragma unroll
        for (int kk = 0; kk < 64; kk += 8) {
            wmma::fragment<wmma::matrix_a, 16, 16, 8, wmma::precision::tf32,
                           wmma::row_major> af;
            wmma::load_matrix_sync(af, &Ss[sr * APAD + kk], APAD);
            wmma::fragment<wmma::matrix_b, 16, 16, 8, wmma::precision::tf32,
                           wmma::row_major> bf0, bf1;
            wmma::load_matrix_sync(bf0, &Vs[kk * APAD + sc],      APAD);
            wmma::load_matrix_sync(bf1, &Vs[kk * APAD + sc + 16], APAD);
            wmma::mma_sync(oacc[0], af, bf0, oacc[0]);
            wmma::mma_sync(oacc[1], af, bf1, oacc[1]);
        }
        __syncthreads();   // (4) all warps done READING P before Ss is reused

        // stage PV into this warp's own (disjoint) Ss region, warp-local readback
        wmma::store_matrix_sync(&Ss[sr * APAD + sc],      oacc[0], APAD,
                                wmma::mem_row_major);
        wmma::store_matrix_sync(&Ss[sr * APAD + sc + 16], oacc[1], APAD,
                                wmma::mem_row_major);
        __syncwarp();

        // ---- O = O * corr + PV (warp-local region: 16 rows x 32 cols) ----
        {
            const int r2 = lane >> 1;            // 0..15
            const int cb = (lane & 1) * 16;      // 0 or 16
            const int row = sr + r2;
            const float corr = corr_s[row];
#pragma unroll
            for (int v = 0; v < 4; v++) {
                const int col = sc + cb + v * 4;
                float4 o = *(float4*)&Os[row * APAD + col];
                float4 p = *(const float4*)&Ss[row * APAD + col];
                o.x = o.x * corr + p.x;
                o.y = o.y * corr + p.y;
                o.z = o.z * corr + p.z;
                o.w = o.w * corr + p.w;
                *(float4*)&Os[row * APAD + col] = o;
            }
        }
        // no loop-top barrier needed: next staging writes Ks/Vs (disjoint from
        // Ss/Os touched here); barrier (1) fences before Ss/Qs are read again.
    }
    __syncthreads();

    // ---- finalize: y[b, qbase+i, h*64+d] = O[i][d] / l[i] ----
    float* yb = g_y + (size_t)b * SEQ * D_MODEL + h * HEAD_DIM;
    for (int idx = tid; idx < 128 * 16; idx += 512) {
        int i = idx >> 4, d4 = (idx & 15) * 4;
        float inv = 1.0f / l_s[i];
        float4 o = *(const float4*)&Os[i * APAD + d4];
        o.x *= inv; o.y *= inv; o.z *= inv; o.w *= inv;
        *(float4*)&yb[(size_t)(qbase + i) * D_MODEL + d4] = o;
    }
}

// ---------------------------------------------------------------------------
// Launch (graph-capturable, allocation-free, no syncs)
// ---------------------------------------------------------------------------
extern "C" void kernel_launch(void* const* d_in, const int* in_sizes, int n_in,
                              void* d_out, int out_size)
{
    (void)in_sizes; (void)n_in; (void)out_size;
    const float* x    = (const float*)d_in[0];
    const float* Wqkv = (const float*)d_in[1];
    const float* bqkv = (const float*)d_in[2];
    const float* Wout = (const float*)d_in[3];
    const float* bout = (const float*)d_in[4];
    float* out = (float*)d_out;

    cudaFuncSetAttribute(attn_kernel, cudaFuncAttributeMaxDynamicSharedMemorySize,
                         ATTN_SMEM_BYTES);

    dim3 g1(C3 / 128, MTOT / 128);           // 24 x 64
    qkv_gemm_kernel<<<g1, 256>>>(x, Wqkv, bqkv);

    dim3 g2(SEQ / 128, BATCH * N_HEADS);     // 16 x 64
    attn_kernel<<<g2, 512, ATTN_SMEM_BYTES>>>();

    dim3 g3(D_MODEL / 128, MTOT / 128);      // 8 x 64
    out_gemm_kernel<<<g3, 256>>>(Wout, bout, out);
}